// round 8
// baseline (speedup 1.0000x reference)
#include <cuda_runtime.h>

#define NS    53       // species
#define ND    54       // state dim
#define NRX   325      // reactions
#define MAXF  16       // max forward-stoich nonzeros per reaction
#define MAXN  24       // max net-stoich nonzeros per reaction
#define MAXS  64       // max net-list entries per species
#define MAXFS 40       // max forward-list entries per species
#define MAXP  32       // max contributions per (k,m) pair
#define BD    192      // threads per block
#define NW    6        // warps per block
#define MSTR  55       // ODD row stride: conflict-free column access
#define KRICH 6        // Richardson iterations (error ~ ||dtJ||^7)
#define RGAS  8.314462618f

// ---- sparse stoichiometry tables (built per launch by prep kernels) ----
__device__ int   g_fcnt[NRX];
__device__ short g_fidx[NRX][MAXF];
__device__ float g_fval[NRX][MAXF];
__device__ int   g_ncnt[NRX];
__device__ short g_nidx[NRX][MAXN];
__device__ float g_nval[NRX][MAXN];
// gather CSRs
__device__ int   g_scnt[NS];            // net list per species
__device__ short g_sj[NS][MAXS];
__device__ float g_snu[NS][MAXS];
__device__ int   g_fscnt[NS];           // forward list per species (for hQ)
__device__ short g_fsj[NS][MAXFS];
__device__ float g_fsv[NS][MAXFS];
__device__ int   g_pcnt[NS * NS];       // (k,m) pair contribution lists
__device__ short g_pj[NS * NS][MAXP];
__device__ float g_pc[NS * NS][MAXP];

__global__ void prep_kernel(const float* __restrict__ nuf,
                            const float* __restrict__ nub) {
    int j = blockIdx.x * blockDim.x + threadIdx.x;
    if (j >= NRX) return;
    int cf = 0, cn = 0;
    for (int k = 0; k < NS; k++) {
        float f = nuf[j * NS + k];
        float b = nub[j * NS + k];
        if (f != 0.0f && cf < MAXF) {
            g_fidx[j][cf] = (short)k; g_fval[j][cf] = f; cf++;
        }
        float net = b - f;
        if (net != 0.0f && cn < MAXN) {
            g_nidx[j][cn] = (short)k; g_nval[j][cn] = net; cn++;
        }
    }
    g_fcnt[j] = cf;
    g_ncnt[j] = cn;
}

__global__ void prep2_kernel(const float* __restrict__ nuf,
                             const float* __restrict__ nub) {
    int k = blockIdx.x * blockDim.x + threadIdx.x;
    if (k >= NS) return;
    int c = 0, c2 = 0;
    for (int j = 0; j < NRX; j++) {
        float f = nuf[j * NS + k];
        float net = nub[j * NS + k] - f;
        if (net != 0.0f && c < MAXS) { g_sj[k][c] = (short)j; g_snu[k][c] = net; c++; }
        if (f != 0.0f && c2 < MAXFS) { g_fsj[k][c2] = (short)j; g_fsv[k][c2] = f; c2++; }
    }
    g_scnt[k] = c;
    g_fscnt[k] = c2;
}

__global__ void prep3_kernel(const float* __restrict__ nuf,
                             const float* __restrict__ nub) {
    int idx = blockIdx.x * blockDim.x + threadIdx.x;
    if (idx >= NS * NS) return;
    int k = idx / NS, m = idx - (idx / NS) * NS;
    int c = 0;
    for (int j = 0; j < NRX; j++) {
        float net = nub[j * NS + k] - nuf[j * NS + k];
        float f   = nuf[j * NS + m];
        if (net != 0.0f && f != 0.0f && c < MAXP) {
            g_pj[idx][c] = (short)j; g_pc[idx][c] = net * f; c++;
        }
    }
    g_pcnt[idx] = c;
}

__global__ __launch_bounds__(BD, 7)
void reactor_kernel(const float* __restrict__ T0,  const float* __restrict__ Pv,
                    const float* __restrict__ Y0,  const float* __restrict__ Wm,
                    const float* __restrict__ nlo, const float* __restrict__ nhi,
                    const float* __restrict__ Tmid,
                    const float* __restrict__ rA,  const float* __restrict__ rB,
                    const float* __restrict__ rE,  const int* __restrict__ nstp,
                    float* __restrict__ out) {
    // Mm holds P = dt*J (54x54); solve (I-P)x = G by x <- G + P x
    __shared__ float Mm[ND][MSTR];
    __shared__ float yn[ND], ycur[ND], gg[ND], xsA[ND], xsB[ND];
    __shared__ float Ws[NS], invW[NS], cpR[NS], hmol[NS], dcpR[NS], Ycs[NS], mY[NS];
    __shared__ float Lc[NS], gC[NS], t0a[NS], wd[NS], uu[NS], vv[NS], hQ[NS], tmp[NS];
    __shared__ float Wor[NS], sm0[NS];
    __shared__ float r_[NRX], rP_[NRX], rT_[NRX], hr_[NRX];
    __shared__ float sT, sMT, sLnT, sIMW, sInvIMW, sRho, sInvRho;
    __shared__ float sCp, sHu, sHv, sHTw, sDcp, sRcp, sdT;

    const int tid  = threadIdx.x;
    const int lane = tid & 31;
    const int b    = blockIdx.x;

    const float P = Pv[0];
    const int n_steps = nstp[0];
    const float dt = 1.0e-6f / (float)n_steps;

    for (int k = tid; k < NS; k += BD) {
        float w = Wm[k];
        Ws[k]   = w;
        invW[k] = 1.0f / w;
        yn[1 + k] = Y0[b * NS + k];
    }
    if (tid == 0) yn[0] = T0[b];
    __syncthreads();

    for (int step = 0; step < n_steps; ++step) {
        for (int i = tid; i < ND; i += BD) ycur[i] = yn[i];
        __syncthreads();

        for (int it = 0; it < 2; ++it) {
            if (tid == 0) {
                float Tr = yn[0];
                float Tc = fminf(fmaxf(Tr, 200.0f), 5000.0f);
                sT = Tc;
                sMT = (Tr > 200.0f && Tr < 5000.0f) ? 1.0f : 0.0f;
                sLnT = logf(Tc);
            }
            __syncthreads();

            const float T = sT;
            const float invT = 1.0f / T;
            // ---- per-species thermo ----
            for (int k = tid; k < NS; k += BD) {
                float Yr = yn[1 + k];
                float Yc = fminf(fmaxf(Yr, 0.0f), 1.0f);
                Ycs[k] = Yc;
                mY[k]  = (Yr > 0.0f && Yr < 1.0f) ? 1.0f : 0.0f;
                const float* a = (T < Tmid[k]) ? (nlo + 7 * k) : (nhi + 7 * k);
                float a0 = a[0], a1 = a[1], a2 = a[2], a3 = a[3], a4 = a[4], a5 = a[5];
                float T2 = T * T, T3 = T2 * T, T4 = T2 * T2;
                cpR[k]  = a0 + a1 * T + a2 * T2 + a3 * T3 + a4 * T4;
                float hRT = a0 + a1 * T * 0.5f + a2 * T2 * (1.0f / 3.0f)
                          + a3 * T3 * 0.25f + a4 * T4 * 0.2f + a5 * invT;
                hmol[k] = hRT * RGAS * T;
                dcpR[k] = a1 + 2.0f * a2 * T + 3.0f * a3 * T2 + 4.0f * a4 * T3;
                tmp[k]  = Yc * invW[k];
            }
            __syncthreads();
            if (tid < 32) {
                float s = (lane < NS ? tmp[lane] : 0.0f)
                        + (lane + 32 < NS ? tmp[lane + 32] : 0.0f);
                for (int o = 16; o; o >>= 1) s += __shfl_xor_sync(0xffffffffu, s, o);
                if (lane == 0) {
                    sIMW = s; sInvIMW = 1.0f / s;
                    float rho = P / (RGAS * T * s);
                    sRho = rho; sInvRho = (RGAS * T * s) / P;
                }
            }
            __syncthreads();
            const float rho = sRho, invRho = sInvRho, invIMW = sInvIMW;
            for (int k = tid; k < NS; k += BD) {
                float iw = invW[k];
                float C  = rho * Ycs[k] * iw;
                float Ce = C + 1e-30f;
                Lc[k]  = logf(Ce);
                gC[k]  = C / Ce;
                t0a[k] = rho * iw / Ce;
                Wor[k] = Ws[k] * invRho;
                sm0[k] = -invIMW * iw;
            }
            __syncthreads();

            // ---- reaction pass: rates + sensitivities (NO atomics) ----
            const float RT = RGAS * T;
            const float invRT = 1.0f / RT;
            for (int j = tid; j < NRX; j += BD) {
                float Aj = rA[j], bj = rB[j], Ej = rE[j];
                float kf = Aj * expf(bj * sLnT - Ej * invRT);
                int nf = g_fcnt[j];
                float sL = 0.0f, Pj = 0.0f;
                for (int e = 0; e < nf; e++) {
                    int k = g_fidx[j][e]; float v = g_fval[j][e];
                    sL += v * Lc[k]; Pj += v * gC[k];
                }
                float r  = kf * expf(sL);
                r_[j]  = r;
                rP_[j] = r * Pj;
                rT_[j] = (r * invT) * (bj + Ej * invRT - Pj);
                float hn = 0.0f;
                int nn = g_ncnt[j];
                for (int e = 0; e < nn; e++)
                    hn += g_nval[j][e] * hmol[g_nidx[j][e]];
                hr_[j] = hn * r;
            }
            __syncthreads();

            // ---- gathers: wd/uu/vv per species; hQ per species ----
            if (tid < NS) {
                const int k = tid;
                float a = 0.0f, u = 0.0f, v = 0.0f;
                const int n = g_scnt[k];
                for (int e = 0; e < n; e++) {
                    int j = g_sj[k][e]; float nu = g_snu[k][e];
                    a += nu * r_[j]; u += nu * rP_[j]; v += nu * rT_[j];
                }
                wd[k] = a; uu[k] = u; vv[k] = v;
            } else if (tid >= 64 && tid < 64 + NS) {
                const int m = tid - 64;
                float s = 0.0f;
                const int n = g_fscnt[m];
                for (int e = 0; e < n; e++)
                    s += g_fsv[m][e] * hr_[g_fsj[m][e]];
                hQ[m] = s;
            }
            __syncthreads();

            // ---- pair gather + fused transform: interior of P = dt*J ----
            for (int idx = tid; idx < NS * NS; idx += BD) {
                const int k = idx / NS, m = idx - k * NS;
                float q = 0.0f;
                const int n = g_pcnt[idx];
                for (int e = 0; e < n; e++)
                    q += g_pc[idx][e] * r_[g_pj[idx][e]];
                float uk = uu[k] - wd[k];
                float J = mY[m] * Wor[k] * (uk * sm0[m] + q * t0a[m]);
                Mm[k + 1][m + 1] = dt * J;
            }
            // ---- scalar reductions (warp 0, after its pair share) ----
            if (tid < 32) {
                float cp = 0, H = 0, hu = 0, hv = 0, hw = 0, dc = 0;
                for (int k = lane; k < NS; k += 32) {
                    float yw = Ycs[k] * invW[k];
                    cp += yw * cpR[k];
                    H  += hmol[k] * wd[k];
                    hu += hmol[k] * uu[k];
                    hv += hmol[k] * vv[k];
                    hw += cpR[k] * wd[k];
                    dc += yw * dcpR[k];
                }
                for (int o = 16; o; o >>= 1) {
                    cp += __shfl_xor_sync(0xffffffffu, cp, o);
                    H  += __shfl_xor_sync(0xffffffffu, H,  o);
                    hu += __shfl_xor_sync(0xffffffffu, hu, o);
                    hv += __shfl_xor_sync(0xffffffffu, hv, o);
                    hw += __shfl_xor_sync(0xffffffffu, hw, o);
                    dc += __shfl_xor_sync(0xffffffffu, dc, o);
                }
                if (lane == 0) {
                    float cpm = RGAS * cp;
                    sCp = cpm; sHu = hu; sHv = hv;
                    sHTw = RGAS * hw; sDcp = RGAS * dc;
                    float rcp = rho * cpm;
                    sRcp = rcp;
                    sdT = -H / rcp;
                }
            }
            __syncthreads();

            // ---- borders (row 0, col 0) and RHS G ----
            const float rcp = sRcp, dTv = sdT, cpm = sCp, huv = sHu;
            const float invCpm = 1.0f / cpm, invRcp = 1.0f / rcp;
            for (int k = tid; k < NS; k += BD) {
                float Jk0 = sMT * Wor[k] * (vv[k] + wd[k] * invT);
                Mm[k + 1][0] = dt * Jk0;
                float sm0k = sm0[k];
                float J0m = mY[k] * (-(huv * sm0k + hQ[k] * t0a[k]) * invRcp
                                     - dTv * (sm0k + cpR[k] * RGAS * invW[k] * invCpm));
                Mm[0][k + 1] = dt * J0m;
                float fk = wd[k] * Wor[k];
                float g  = yn[1 + k] - ycur[1 + k] - dt * fk;
                gg[1 + k]  = g;
                xsA[1 + k] = g;
            }
            if (tid == 0) {
                float J00 = sMT * (-(sHTw + sHv) / rcp
                                   - dTv * (-invT + sDcp / cpm));
                Mm[0][0] = dt * J00;
                float g0 = yn[0] - ycur[0] - dt * dTv;
                gg[0]  = g0;
                xsA[0] = g0;
            }
            __syncthreads();

            // ---- Richardson solve: x <- G + P x (thread-per-row, no shfl) ----
            if (tid < 64) {
                const int r = tid;
                const bool act = (r < ND);
                float grr = act ? gg[r] : 0.0f;
                #pragma unroll
                for (int m = 0; m < KRICH; m++) {
                    const float* xin = (m & 1) ? xsB : xsA;
                    float*       xout = (m & 1) ? xsA : xsB;
                    if (act) {
                        float s0 = 0.0f, s1 = 0.0f;
                        #pragma unroll
                        for (int c = 0; c < ND; c += 2) {
                            s0 += Mm[r][c]     * xin[c];
                            s1 += Mm[r][c + 1] * xin[c + 1];
                        }
                        xout[r] = grr + s0 + s1;
                    }
                    asm volatile("bar.sync 1, 64;" ::: "memory");
                }
            }
            __syncthreads();
            // KRICH even -> final x in xsA
            for (int i = tid; i < ND; i += BD) yn[i] -= xsA[i];
            __syncthreads();
        } // newton
    } // steps

    for (int i = tid; i < ND; i += BD) out[b * ND + i] = yn[i];
}

extern "C" void kernel_launch(void* const* d_in, const int* in_sizes, int n_in,
                              void* d_out, int out_size) {
    const float* T0  = (const float*)d_in[0];
    const float* P   = (const float*)d_in[1];
    const float* Y0  = (const float*)d_in[2];
    const float* W   = (const float*)d_in[3];
    const float* nlo = (const float*)d_in[4];
    const float* nhi = (const float*)d_in[5];
    const float* Tm  = (const float*)d_in[6];
    const float* A   = (const float*)d_in[7];
    const float* Bc  = (const float*)d_in[8];
    const float* E   = (const float*)d_in[9];
    const float* nf  = (const float*)d_in[10];
    const float* nb  = (const float*)d_in[11];
    const int*   ns  = (const int*)d_in[12];
    const int B = in_sizes[0];

    prep_kernel<<<(NRX + 127) / 128, 128>>>(nf, nb);
    prep2_kernel<<<1, 64>>>(nf, nb);
    prep3_kernel<<<(NS * NS + 127) / 128, 128>>>(nf, nb);
    reactor_kernel<<<B, BD>>>(T0, P, Y0, W, nlo, nhi, Tm, A, Bc, E, ns, (float*)d_out);
}